// round 17
// baseline (speedup 1.0000x reference)
#include <cuda_runtime.h>
#include <cuda_bf16.h>
#include <cstdint>

// ---------------- Problem sizes ----------------
#define TOKENS 4096
#define IN_F   8192
#define OUT_F  8192

#define KITERS   (IN_F / 64)            // 128
#define NTILES   (OUT_F / 128)          // 64
#define MTILES   (TOKENS / 128)         // 32

// ---- bf16 GEMM staging: CTA 128x128, 4 warps (64x64 each), 2 CTAs/SM ----
#define ROWB        144                 // 128B data + 16B pad (bank stride 36 -> conflict-free)
#define A_STAGE_B   (128 * ROWB)        // 18432
#define STAGE_B     (2 * A_STAGE_B)     // 36864
#define NSTAGES_B   3
#define GEMM_SMEM_B (NSTAGES_B * STAGE_B)   // 110592 -> 2 CTAs/SM (221 KB)

// ---------------- Scratch (ROW-MAJOR: prep writes coalesced; GEMM absorbs stride) ----------------
__device__ __nv_bfloat16  g_Ab[(size_t)TOKENS * IN_F];   // 64 MB, row-major [t][k]
__device__ __nv_bfloat16  g_Bb[(size_t)OUT_F  * IN_F];   // 128 MB, row-major [n][k]
__device__ float          g_s[TOKENS];

// ---------------- PTX helpers ----------------
__device__ __forceinline__ uint32_t smem_to_u32(const void* smem_ptr) {
    uint32_t addr;
    asm("{ .reg .u64 tmp; cvta.to.shared.u64 tmp, %1; cvt.u32.u64 %0, tmp; }"
        : "=r"(addr) : "l"(smem_ptr));
    return addr;
}

#define CP_ASYNC16(dst, src) \
    asm volatile("cp.async.cg.shared.global [%0], [%1], 16;" \
        :: "r"((uint32_t)(dst)), "l"(src) : "memory")
#define CP_COMMIT() asm volatile("cp.async.commit_group;" ::: "memory")
#define CP_WAIT1()  asm volatile("cp.async.wait_group 1;" ::: "memory")

#define MMA_BF16(c, a, b0, b1) \
    asm volatile( \
        "mma.sync.aligned.m16n8k16.row.col.f32.bf16.bf16.f32 " \
        "{%0,%1,%2,%3}, {%4,%5,%6,%7}, {%8,%9}, {%0,%1,%2,%3};" \
        : "+f"((c)[0]), "+f"((c)[1]), "+f"((c)[2]), "+f"((c)[3]) \
        : "r"((a)[0]), "r"((a)[1]), "r"((a)[2]), "r"((a)[3]), \
          "r"(b0), "r"(b1))

#define LDMX4(r, addr) \
    asm volatile("ldmatrix.sync.aligned.m8n8.x4.shared.b16 {%0,%1,%2,%3}, [%4];" \
        : "=r"((r)[0]), "=r"((r)[1]), "=r"((r)[2]), "=r"((r)[3]) \
        : "r"((uint32_t)(addr)))

// ---------------- Kernel 1: merged prep, fully coalesced row-major output ----------------
// Blocks [0, TOKENS): quantize one token row -> bf16 row + scale.
// Blocks [TOKENS, TOKENS+OUT_F): convert one weight row -> bf16 row.
__global__ void __launch_bounds__(256, 1) prep_kernel(
    const float* __restrict__ x, const int* __restrict__ w
) {
    int b = blockIdx.x;
    int tid = threadIdx.x;
    int k0 = tid * 32;

    if (b < TOKENS) {
        int t = b;
        const float4* xr = reinterpret_cast<const float4*>(x + (size_t)t * IN_F) + tid * 8;

        float vv[32];
        float m = 0.0f;
#pragma unroll
        for (int j = 0; j < 8; j++) {
            float4 v4 = xr[j];
            vv[4 * j + 0] = v4.x; vv[4 * j + 1] = v4.y;
            vv[4 * j + 2] = v4.z; vv[4 * j + 3] = v4.w;
            m = fmaxf(m, fmaxf(fmaxf(fabsf(v4.x), fabsf(v4.y)), fmaxf(fabsf(v4.z), fabsf(v4.w))));
        }
#pragma unroll
        for (int o = 16; o > 0; o >>= 1)
            m = fmaxf(m, __shfl_xor_sync(0xFFFFFFFFu, m, o));

        __shared__ float wm_[8];
        __shared__ float sh_s;
        if ((tid & 31) == 0) wm_[tid >> 5] = m;
        __syncthreads();
        if (tid == 0) {
            float mm = wm_[0];
#pragma unroll
            for (int j = 1; j < 8; j++) mm = fmaxf(mm, wm_[j]);
            float s = 127.0f / fmaxf(mm, 1e-5f);
            g_s[t] = s;
            sh_s = s;
        }
        __syncthreads();
        float s = sh_s;

        char* dst = reinterpret_cast<char*>(g_Ab) + ((size_t)t * IN_F + k0) * 2;
        uint32_t pk[16];
#pragma unroll
        for (int p = 0; p < 16; p++) {
            float qa = fminf(fmaxf(rintf(vv[2 * p + 0] * s), -128.0f), 127.0f);
            float qb = fminf(fmaxf(rintf(vv[2 * p + 1] * s), -128.0f), 127.0f);
            __nv_bfloat162 h = __floats2bfloat162_rn(qa, qb);
            pk[p] = *reinterpret_cast<uint32_t*>(&h);
        }
        uint4* d4 = reinterpret_cast<uint4*>(dst);
#pragma unroll
        for (int j = 0; j < 4; j++)
            d4[j] = make_uint4(pk[4 * j], pk[4 * j + 1], pk[4 * j + 2], pk[4 * j + 3]);
    } else {
        int n = b - TOKENS;
        const int4* wr = reinterpret_cast<const int4*>(w + (size_t)n * IN_F + k0);

        char* dst = reinterpret_cast<char*>(g_Bb) + ((size_t)n * IN_F + k0) * 2;
        uint32_t pk[16];
#pragma unroll
        for (int p = 0; p < 8; p++) {
            int4 q = wr[p];
            __nv_bfloat162 h0 = __floats2bfloat162_rn((float)q.x, (float)q.y);
            __nv_bfloat162 h1 = __floats2bfloat162_rn((float)q.z, (float)q.w);
            pk[2 * p + 0] = *reinterpret_cast<uint32_t*>(&h0);
            pk[2 * p + 1] = *reinterpret_cast<uint32_t*>(&h1);
        }
        uint4* d4 = reinterpret_cast<uint4*>(dst);
#pragma unroll
        for (int j = 0; j < 4; j++)
            d4[j] = make_uint4(pk[4 * j], pk[4 * j + 1], pk[4 * j + 2], pk[4 * j + 3]);
    }
}

// ---------------- Kernel 2: bf16 HMMA GEMM, CTA 128x128, 4 warps (64x64 each) ----------------
// 2 CTAs/SM. wm = wid&1 (64 M-rows), wn = wid>>1 (64 N-cols). [R11/R13 body, verified]
// Sources are row-major: stage kt loads 128 rows x 128 bytes, row stride IN_F*2.
__global__ void __launch_bounds__(128, 1) gemm_bf_kernel(
    const float* __restrict__ wscale,
    const float* __restrict__ bias,
    float* __restrict__ out
) {
    extern __shared__ char smem[];
    uint32_t sb = smem_to_u32(smem);
    int tid = threadIdx.x, wid = tid >> 5, lane = tid & 31;
    int wm = wid & 1, wn = wid >> 1;
    int g = lane >> 2, tig = lane & 3;

    int n_t = blockIdx.x;   // 0..63
    int m_t = blockIdx.y;   // 0..31

    const char* Ag = reinterpret_cast<const char*>(g_Ab) + (size_t)m_t * 128 * IN_F * 2;
    const char* Bg = reinterpret_cast<const char*>(g_Bb) + (size_t)n_t * 128 * IN_F * 2;
    const size_t ROW_GSTRIDE = (size_t)IN_F * 2;   // 16384 bytes

    int quad = lane >> 3, lr = lane & 7;
    uint32_t a_off = (uint32_t)((wm * 64 + (quad & 1) * 8 + lr) * ROWB + (quad >> 1) * 16);
    uint32_t b_off = (uint32_t)(A_STAGE_B + (wn * 64 + (quad >> 1) * 8 + lr) * ROWB + (quad & 1) * 16);

    float acc[4][8][4];
#pragma unroll
    for (int mb = 0; mb < 4; mb++)
#pragma unroll
        for (int nb = 0; nb < 8; nb++)
#pragma unroll
            for (int i = 0; i < 4; i++) acc[mb][nb][i] = 0.0f;

    // per-thread fixed (row, col-chunk) assignment: 8 chunks/thread, rows tid>>3 + 16*j
    int tr = tid >> 3, tc = tid & 7;

#pragma unroll
    for (int p = 0; p < NSTAGES_B - 1; p++) {
        uint32_t dstA = sb + p * STAGE_B;
        uint32_t dstB = dstA + A_STAGE_B;
        const char* srcA = Ag + (size_t)p * 128;
        const char* srcB = Bg + (size_t)p * 128;
#pragma unroll
        for (int j = 0; j < 8; j++) {
            int r = j * 16 + tr;
            CP_ASYNC16(dstA + r * ROWB + tc * 16, srcA + r * ROW_GSTRIDE + tc * 16);
            CP_ASYNC16(dstB + r * ROWB + tc * 16, srcB + r * ROW_GSTRIDE + tc * 16);
        }
        CP_COMMIT();
    }

    for (int kt = 0; kt < KITERS; kt++) {
        CP_WAIT1();
        __syncthreads();
        int kn = kt + NSTAGES_B - 1;
        if (kn < KITERS) {
            int sn = kn % NSTAGES_B;
            uint32_t dstA = sb + sn * STAGE_B;
            uint32_t dstB = dstA + A_STAGE_B;
            const char* srcA = Ag + (size_t)kn * 128;
            const char* srcB = Bg + (size_t)kn * 128;
#pragma unroll
            for (int j = 0; j < 8; j++) {
                int r = j * 16 + tr;
                CP_ASYNC16(dstA + r * ROWB + tc * 16, srcA + r * ROW_GSTRIDE + tc * 16);
                CP_ASYNC16(dstB + r * ROWB + tc * 16, srcB + r * ROW_GSTRIDE + tc * 16);
            }
        }
        CP_COMMIT();

        uint32_t stb = sb + (kt % NSTAGES_B) * STAGE_B;
#pragma unroll
        for (int ks = 0; ks < 4; ks++) {           // 4 x k16 per 64-elem stage
            uint32_t ko = (uint32_t)(ks * 32);
            uint32_t a[4][4];
#pragma unroll
            for (int mb = 0; mb < 4; mb++)
                LDMX4(a[mb], stb + a_off + mb * 16 * ROWB + ko);
#pragma unroll
            for (int nbp = 0; nbp < 4; nbp++) {    // each covers 2 n-blocks
                uint32_t b[4];
                LDMX4(b, stb + b_off + nbp * 16 * ROWB + ko);
#pragma unroll
                for (int mb = 0; mb < 4; mb++) {
                    MMA_BF16(acc[mb][2 * nbp + 0], a[mb], b[0], b[1]);
                    MMA_BF16(acc[mb][2 * nbp + 1], a[mb], b[2], b[3]);
                }
            }
        }
    }

    // ---- epilogue: dequant + bias ----
    float wsc = wscale[0];
#pragma unroll
    for (int mb = 0; mb < 4; mb++) {
        int r_a = m_t * 128 + wm * 64 + mb * 16 + g;
        int r_b = r_a + 8;
        float sca = 1.0f / (g_s[r_a] * wsc);
        float scb = 1.0f / (g_s[r_b] * wsc);
        float* outa = out + (size_t)r_a * OUT_F;
        float* outb = out + (size_t)r_b * OUT_F;
#pragma unroll
        for (int nb = 0; nb < 8; nb++) {
            int col = n_t * 128 + wn * 64 + nb * 8 + tig * 2;
            float2 bi = *reinterpret_cast<const float2*>(bias + col);
            float2 o;
            o.x = acc[mb][nb][0] * sca + bi.x;
            o.y = acc[mb][nb][1] * sca + bi.y;
            *reinterpret_cast<float2*>(outa + col) = o;
            o.x = acc[mb][nb][2] * scb + bi.x;
            o.y = acc[mb][nb][3] * scb + bi.y;
            *reinterpret_cast<float2*>(outb + col) = o;
        }
    }
}

// ---------------- Launch ----------------
extern "C" void kernel_launch(void* const* d_in, const int* in_sizes, int n_in,
                              void* d_out, int out_size) {
    const float* x      = (const float*)d_in[0];
    const int*   weight = (const int*)d_in[1];
    const float* wscale = (const float*)d_in[2];
    const float* bias   = (const float*)d_in[3];
    float*       out    = (float*)d_out;

    prep_kernel<<<TOKENS + OUT_F, 256>>>(x, weight);

    cudaFuncSetAttribute(gemm_bf_kernel, cudaFuncAttributeMaxDynamicSharedMemorySize, GEMM_SMEM_B);
    gemm_bf_kernel<<<dim3(NTILES, MTILES), 128, GEMM_SMEM_B>>>(wscale, bias, out);
}